// round 11
// baseline (speedup 1.0000x reference)
#include <cuda_runtime.h>

typedef unsigned long long u64;

// ---- packed fp32x2 helpers (sm_100+; ptxas never emits these from C++) ----
static __device__ __forceinline__ u64 pack2(float x) {
    u64 r; asm("mov.b64 %0, {%1, %1};" : "=l"(r) : "f"(x)); return r;
}
static __device__ __forceinline__ u64 fma2(u64 a, u64 b, u64 c) {
    u64 d; asm("fma.rn.f32x2 %0, %1, %2, %3;" : "=l"(d) : "l"(a), "l"(b), "l"(c)); return d;
}
static __device__ __forceinline__ u64 add2(u64 a, u64 b) {
    u64 d; asm("add.rn.f32x2 %0, %1, %2;" : "=l"(d) : "l"(a), "l"(b)); return d;
}

#define B_  2
#define H_  96
#define W_  128
#define D_  32
#define C_  16
#define F_  16
#define TW  8
#define NSLAB 30
#define DSTR  17                    // [d][c]: c stride 1, d stride 16+1 pad
#define SSTR  561                   // 33 rows * 17 (row 32 = dv row)
#define DVROW 544                   // 32*17
#define IMG_FLOATS (NSLAB * SSTR)   // 16830
#define WOFF   16832                // 16B-aligned weight base
#define WFLOATS (27 * 16 * 16)      // 6912
#define BPOFF  (WOFF + WFLOATS)     // 23744
#define SMEM_FLOATS (BPOFF + 32)    // 23776 floats = 95,104 B -> 2 CTAs/SM

extern __shared__ float smem[];

__global__ __launch_bounds__(256, 2)
void sparse_conv3d_kernel(const float* __restrict__ images,
                          const int*   __restrict__ bp,
                          const float* __restrict__ kern,
                          const float* __restrict__ defv,
                          float*       __restrict__ out)
{
    float* s_img = smem;            // [slab][33 rows][17] ; row 32 = dv row
    float* s_w   = smem + WOFF;     // natural [tap][c][f]
    int*   s_bp  = (int*)(smem + BPOFF);

    const int tid = threadIdx.x;    // 256 threads
    const int b   = blockIdx.z;
    const int h   = blockIdx.y;
    const int w0  = blockIdx.x * TW;
    const float dv = defv[0];

    // ---- stage weights: straight copy, natural layout ----
    for (int idx = tid; idx < WFLOATS / 4; idx += 256) {
        ((float4*)s_w)[idx] = ((const float4*)kern)[idx];
    }
    // ---- dv rows: 30 slabs x 16 c ----
    for (int idx = tid; idx < NSLAB * 16; idx += 256) {
        int s = idx >> 4, c = idx & 15;
        s_img[s * SSTR + DVROW + c] = dv;
    }
    // ---- base planes for 3x10 neighborhood ----
    if (tid < NSLAB) {
        int r  = tid / 10, q = tid - r * 10;
        int hc = min(max(h + r - 1, 0), H_ - 1);
        int wc = min(max(w0 + q - 1, 0), W_ - 1);
        s_bp[tid] = bp[(b * H_ + hc) * W_ + wc];
    }
    // ---- stage 30 slabs as [d][c]; spatially invalid slabs = dv ----
    {
        const int d  = tid >> 3;          // 0..31
        const int c2 = (tid & 7) * 2;     // 0,2,..,14
        int s = 0;
        #pragma unroll 1
        for (int r = 0; r < 3; ++r) {
            const int  hn = h + r - 1;
            const bool vh = (unsigned)hn < (unsigned)H_;
            #pragma unroll 1
            for (int q = 0; q < 10; ++q, ++s) {
                const int wn = w0 + q - 1;
                float2 v;
                if (vh && (unsigned)wn < (unsigned)W_) {
                    v = *(const float2*)&images[
                        ((((size_t)b * H_ + hn) * W_ + wn) * D_ + d) * C_ + c2];
                } else {
                    v = make_float2(dv, dv);
                }
                float* p = s_img + s * SSTR + d * DSTR + c2;
                p[0] = v.x; p[1] = v.y;
            }
        }
    }
    __syncthreads();

    // ---- compute: thread = 2 w-cols x 8 d x 4 f, cgrp = c-quarter (4 c's) ----
    const int tp    = tid & 63;
    const int cgrp  = tid >> 6;       // 0..3: c in [4cgrp, 4cgrp+4)
    const int wlp   = tp & 3;         // column pair: cols {2wlp, 2wlp+1}
    const int fq    = (tp >> 2) & 3;  // f in [4fq, 4fq+4)
    const int dg    = tp >> 4;        // 0..3 -> d in [8dg, 8dg+8)
    const int dbase = dg * 8;
    const int cbase = cgrp * 4;
    const int colA  = 2 * wlp;
    const int colB  = colA + 1;
    const int bpA   = s_bp[11 + colA];
    const int bpB   = s_bp[11 + colB];

    u64 accA[8][2], accB[8][2];
    #pragma unroll
    for (int t = 0; t < 8; ++t) {
        accA[t][0] = 0ull; accA[t][1] = 0ull;
        accB[t][0] = 0ull; accB[t][1] = 0ull;
    }

    #pragma unroll 1
    for (int i = 0; i < 3; ++i) {
        #pragma unroll 1
        for (int j = 0; j < 3; ++j) {
            const int sA   = i * 10 + colA + j;
            const int sB   = sA + 1;
            const int relA = bpA - s_bp[sA];
            const int relB = bpB - s_bp[sB];
            int xoffA[10], xoffB[10];
            #pragma unroll
            for (int u = 0; u < 10; ++u) {
                int ddA  = dbase + relA - 1 + u;
                int ddB  = dbase + relB - 1 + u;
                int rowA = ((unsigned)ddA < (unsigned)D_) ? ddA : 32;
                int rowB = ((unsigned)ddB < (unsigned)D_) ? ddB : 32;
                xoffA[u] = sA * SSTR + rowA * DSTR + cbase;
                xoffB[u] = sB * SSTR + rowB * DSTR + cbase;
            }
            const float* wp = s_w + (i * 3 + j) * 768 + cbase * 16 + fq * 4;
            #pragma unroll 1
            for (int cc = 0; cc < 4; ++cc) {
                // weights for 3 k-taps, this c, this f-quarter (reused 16x each)
                const float* wc = wp + cc * 16;
                ulonglong2 wk0 = *(const ulonglong2*)(wc);
                ulonglong2 wk1 = *(const ulonglong2*)(wc + 256);
                ulonglong2 wk2 = *(const ulonglong2*)(wc + 512);
                // column A
                {
                    u64 X[10];
                    #pragma unroll
                    for (int u = 0; u < 10; ++u)
                        X[u] = pack2(s_img[xoffA[u] + cc]);
                    #pragma unroll
                    for (int t = 0; t < 8; ++t) {
                        accA[t][0] = fma2(X[t],     wk0.x, accA[t][0]);
                        accA[t][1] = fma2(X[t],     wk0.y, accA[t][1]);
                        accA[t][0] = fma2(X[t + 1], wk1.x, accA[t][0]);
                        accA[t][1] = fma2(X[t + 1], wk1.y, accA[t][1]);
                        accA[t][0] = fma2(X[t + 2], wk2.x, accA[t][0]);
                        accA[t][1] = fma2(X[t + 2], wk2.y, accA[t][1]);
                    }
                }
                // column B
                {
                    u64 X[10];
                    #pragma unroll
                    for (int u = 0; u < 10; ++u)
                        X[u] = pack2(s_img[xoffB[u] + cc]);
                    #pragma unroll
                    for (int t = 0; t < 8; ++t) {
                        accB[t][0] = fma2(X[t],     wk0.x, accB[t][0]);
                        accB[t][1] = fma2(X[t],     wk0.y, accB[t][1]);
                        accB[t][0] = fma2(X[t + 1], wk1.x, accB[t][0]);
                        accB[t][1] = fma2(X[t + 1], wk1.y, accB[t][1]);
                        accB[t][0] = fma2(X[t + 2], wk2.x, accB[t][0]);
                        accB[t][1] = fma2(X[t + 2], wk2.y, accB[t][1]);
                    }
                }
            }
        }
    }

    // ---- reduce c-split: cgrps 1..3 stage 32 u64 each, cgrp0 adds + stores ----
    __syncthreads();                       // slabs dead; reuse as staging
    u64* s_red = (u64*)smem;               // 3 regions x (64 threads x 34 u64)
    if (cgrp != 0) {
        u64* dst = s_red + (cgrp - 1) * 2176 + tp * 34;
        #pragma unroll
        for (int t = 0; t < 8; ++t) {
            *(ulonglong2*)(dst + t * 2)      = make_ulonglong2(accA[t][0], accA[t][1]);
            *(ulonglong2*)(dst + 16 + t * 2) = make_ulonglong2(accB[t][0], accB[t][1]);
        }
    }
    __syncthreads();
    if (cgrp == 0) {
        const u64* r0 = s_red + tp * 34;
        const u64* r1 = r0 + 2176;
        const u64* r2 = r1 + 2176;
        const size_t baseA = ((((size_t)b * H_ + h) * W_ + (w0 + colA)) * D_) * (size_t)F_;
        const size_t baseB = ((((size_t)b * H_ + h) * W_ + (w0 + colB)) * D_) * (size_t)F_;
        #pragma unroll
        for (int t = 0; t < 8; ++t) {
            ulonglong2 a0 = *(const ulonglong2*)(r0 + t * 2);
            ulonglong2 a1 = *(const ulonglong2*)(r1 + t * 2);
            ulonglong2 a2 = *(const ulonglong2*)(r2 + t * 2);
            u64 sA0 = add2(add2(accA[t][0], a0.x), add2(a1.x, a2.x));
            u64 sA1 = add2(add2(accA[t][1], a0.y), add2(a1.y, a2.y));
            ulonglong2 b0 = *(const ulonglong2*)(r0 + 16 + t * 2);
            ulonglong2 b1 = *(const ulonglong2*)(r1 + 16 + t * 2);
            ulonglong2 b2 = *(const ulonglong2*)(r2 + 16 + t * 2);
            u64 sB0 = add2(add2(accB[t][0], b0.x), add2(b1.x, b2.x));
            u64 sB1 = add2(add2(accB[t][1], b0.y), add2(b1.y, b2.y));
            float* oA = out + baseA + (size_t)(dbase + t) * F_ + fq * 4;
            float* oB = out + baseB + (size_t)(dbase + t) * F_ + fq * 4;
            *(ulonglong2*)oA = make_ulonglong2(sA0, sA1);
            *(ulonglong2*)oB = make_ulonglong2(sB0, sB1);
        }
    }
}

extern "C" void kernel_launch(void* const* d_in, const int* in_sizes, int n_in,
                              void* d_out, int out_size)
{
    // Identify inputs by element count (robust to metadata order):
    // images 12,582,912 | base_plane 24,576 | kernel 6,912 | default 1
    const float* images = nullptr;
    const int*   bp     = nullptr;
    const float* kern   = nullptr;
    const float* defv   = nullptr;
    for (int i = 0; i < n_in; ++i) {
        switch (in_sizes[i]) {
            case 12582912: images = (const float*)d_in[i]; break;
            case 24576:    bp     = (const int*)  d_in[i]; break;
            case 6912:     kern   = (const float*)d_in[i]; break;
            case 1:        defv   = (const float*)d_in[i]; break;
            default: break;
        }
    }
    if (!images) images = (const float*)d_in[0];
    if (!bp)     bp     = (const int*)  d_in[1];
    if (!kern)   kern   = (const float*)d_in[2];
    if (!defv)   defv   = (const float*)d_in[3];

    const int smem_bytes = SMEM_FLOATS * 4;
    (void)cudaFuncSetAttribute(sparse_conv3d_kernel,
                               cudaFuncAttributeMaxDynamicSharedMemorySize, smem_bytes);

    dim3 grid(W_ / TW, H_, B_);   // (16, 96, 2)
    sparse_conv3d_kernel<<<grid, 256, smem_bytes>>>(
        images, bp, kern, defv, (float*)d_out);
}

// round 12
// speedup vs baseline: 1.1197x; 1.1197x over previous
#include <cuda_runtime.h>

typedef unsigned long long u64;

// ---- packed fp32x2 helpers (sm_100+; ptxas never emits these from C++) ----
static __device__ __forceinline__ u64 pack2(float x) {
    u64 r; asm("mov.b64 %0, {%1, %1};" : "=l"(r) : "f"(x)); return r;
}
static __device__ __forceinline__ u64 fma2(u64 a, u64 b, u64 c) {
    u64 d; asm("fma.rn.f32x2 %0, %1, %2, %3;" : "=l"(d) : "l"(a), "l"(b), "l"(c)); return d;
}
static __device__ __forceinline__ u64 add2(u64 a, u64 b) {
    u64 d; asm("add.rn.f32x2 %0, %1, %2;" : "=l"(d) : "l"(a), "l"(b)); return d;
}

#define B_  2
#define H_  96
#define W_  128
#define D_  32
#define C_  16
#define F_  16
#define TW  8
#define TH  4                       // output h-rows per CTA
#define NSROW 6                     // slab rows (TH + 2 halo)
#define NSLAB 60                    // 6 x 10
#define DSTR  17                    // [d][c]: c stride 1, d stride 16+1 pad
#define SSTR  561                   // 33 rows * 17 (row 32 = dv row)
#define DVROW 544                   // 32*17
#define IMG_FLOATS (NSLAB * SSTR)   // 33660
#define WOFF   33664                // 16B-aligned weight base
#define WFLOATS (27 * 16 * 16)      // 6912
#define BPOFF  (WOFF + WFLOATS)     // 40576
#define SMEM_FLOATS (BPOFF + 64)    // 40640 floats = 162,560 B -> 1 CTA/SM

extern __shared__ float smem[];

__global__ __launch_bounds__(512, 1)
void sparse_conv3d_kernel(const float* __restrict__ images,
                          const int*   __restrict__ bp,
                          const float* __restrict__ kern,
                          const float* __restrict__ defv,
                          float*       __restrict__ out)
{
    float* s_img = smem;            // [slab][33 rows][17] ; row 32 = dv row
    float* s_w   = smem + WOFF;     // natural [tap][c][f]
    int*   s_bp  = (int*)(smem + BPOFF);

    const int tid = threadIdx.x;    // 512 threads
    const int b   = blockIdx.z;
    const int h0  = blockIdx.y * TH;
    const int w0  = blockIdx.x * TW;
    const float dv = defv[0];

    // ---- stage weights: straight copy, natural layout ----
    for (int idx = tid; idx < WFLOATS / 4; idx += 512) {
        ((float4*)s_w)[idx] = ((const float4*)kern)[idx];
    }
    // ---- dv rows: 60 slabs x 16 c ----
    for (int idx = tid; idx < NSLAB * 16; idx += 512) {
        int s = idx >> 4, c = idx & 15;
        s_img[s * SSTR + DVROW + c] = dv;
    }
    // ---- base planes for 6x10 neighborhood ----
    if (tid < NSLAB) {
        int r  = tid / 10, q = tid - r * 10;
        int hc = min(max(h0 + r - 1, 0), H_ - 1);
        int wc = min(max(w0 + q - 1, 0), W_ - 1);
        s_bp[tid] = bp[(b * H_ + hc) * W_ + wc];
    }
    // ---- stage 60 slabs as [d][c]; spatially invalid slabs = dv ----
    // unit u = (slab, d, c4): 60 * 32 * 4 = 7680 float4 units
    for (int u = tid; u < NSLAB * 128; u += 512) {
        const int s  = u >> 7;
        const int d  = (u >> 2) & 31;
        const int c4 = (u & 3) * 4;
        const int r  = s / 10, q = s - r * 10;
        const int hn = h0 + r - 1;
        const int wn = w0 + q - 1;
        float4 v;
        if ((unsigned)hn < (unsigned)H_ && (unsigned)wn < (unsigned)W_) {
            v = *(const float4*)&images[
                ((((size_t)b * H_ + hn) * W_ + wn) * D_ + d) * C_ + c4];
        } else {
            v = make_float4(dv, dv, dv, dv);
        }
        float* p = s_img + s * SSTR + d * DSTR + c4;
        p[0] = v.x; p[1] = v.y; p[2] = v.z; p[3] = v.w;
    }
    __syncthreads();

    // ---- compute: hr(4) x cgrp(2) x [wlp(4) x fq(4) x dg(4)] ----
    const int hr    = tid >> 7;       // output row within tile
    const int t7    = tid & 127;
    const int cgrp  = t7 >> 6;        // 0: c 0-7, 1: c 8-15
    const int tp    = t7 & 63;
    const int wlp   = tp & 3;         // column pair: cols {2wlp, 2wlp+1}
    const int fq    = (tp >> 2) & 3;  // f in [4fq, 4fq+4)
    const int dg    = tp >> 4;        // 0..3 -> d in [8dg, 8dg+8)
    const int dbase = dg * 8;
    const int cbase = cgrp * 8;
    const int colA  = 2 * wlp;
    const int colB  = colA + 1;
    const int bpA   = s_bp[(hr + 1) * 10 + 1 + colA];
    const int bpB   = s_bp[(hr + 1) * 10 + 1 + colB];

    u64 accA[8][2], accB[8][2];
    #pragma unroll
    for (int t = 0; t < 8; ++t) {
        accA[t][0] = 0ull; accA[t][1] = 0ull;
        accB[t][0] = 0ull; accB[t][1] = 0ull;
    }

    #pragma unroll 1
    for (int i = 0; i < 3; ++i) {
        #pragma unroll 1
        for (int j = 0; j < 3; ++j) {
            const int sA   = (hr + i) * 10 + colA + j;
            const int sB   = sA + 1;
            const int relA = bpA - s_bp[sA];
            const int relB = bpB - s_bp[sB];
            int xoffA[10], xoffB[10];
            #pragma unroll
            for (int u = 0; u < 10; ++u) {
                int ddA  = dbase + relA - 1 + u;
                int ddB  = dbase + relB - 1 + u;
                int rowA = ((unsigned)ddA < (unsigned)D_) ? ddA : 32;
                int rowB = ((unsigned)ddB < (unsigned)D_) ? ddB : 32;
                xoffA[u] = sA * SSTR + rowA * DSTR + cbase;
                xoffB[u] = sB * SSTR + rowB * DSTR + cbase;
            }
            const float* wp = s_w + (i * 3 + j) * 768 + cbase * 16 + fq * 4;
            #pragma unroll 1
            for (int cc = 0; cc < 8; ++cc) {
                // weights for 3 k-taps, this c, this f-quarter (reused 16x each)
                const float* wc = wp + cc * 16;
                ulonglong2 wk0 = *(const ulonglong2*)(wc);
                ulonglong2 wk1 = *(const ulonglong2*)(wc + 256);
                ulonglong2 wk2 = *(const ulonglong2*)(wc + 512);
                // column A
                {
                    u64 X[10];
                    #pragma unroll
                    for (int u = 0; u < 10; ++u)
                        X[u] = pack2(s_img[xoffA[u] + cc]);
                    #pragma unroll
                    for (int t = 0; t < 8; ++t) {
                        accA[t][0] = fma2(X[t],     wk0.x, accA[t][0]);
                        accA[t][1] = fma2(X[t],     wk0.y, accA[t][1]);
                        accA[t][0] = fma2(X[t + 1], wk1.x, accA[t][0]);
                        accA[t][1] = fma2(X[t + 1], wk1.y, accA[t][1]);
                        accA[t][0] = fma2(X[t + 2], wk2.x, accA[t][0]);
                        accA[t][1] = fma2(X[t + 2], wk2.y, accA[t][1]);
                    }
                }
                // column B
                {
                    u64 X[10];
                    #pragma unroll
                    for (int u = 0; u < 10; ++u)
                        X[u] = pack2(s_img[xoffB[u] + cc]);
                    #pragma unroll
                    for (int t = 0; t < 8; ++t) {
                        accB[t][0] = fma2(X[t],     wk0.x, accB[t][0]);
                        accB[t][1] = fma2(X[t],     wk0.y, accB[t][1]);
                        accB[t][0] = fma2(X[t + 1], wk1.x, accB[t][0]);
                        accB[t][1] = fma2(X[t + 1], wk1.y, accB[t][1]);
                        accB[t][0] = fma2(X[t + 2], wk2.x, accB[t][0]);
                        accB[t][1] = fma2(X[t + 2], wk2.y, accB[t][1]);
                    }
                }
            }
        }
    }

    // ---- reduce c-split: cgrp1 stages 32 u64, cgrp0 adds + stores ----
    __syncthreads();                       // slabs dead; reuse as staging
    u64* s_red = (u64*)smem;               // 256 threads x 34 u64 stride (16B aligned)
    const int rid = hr * 64 + tp;
    if (cgrp == 1) {
        u64* dst = s_red + rid * 34;
        #pragma unroll
        for (int t = 0; t < 8; ++t) {
            *(ulonglong2*)(dst + t * 2)      = make_ulonglong2(accA[t][0], accA[t][1]);
            *(ulonglong2*)(dst + 16 + t * 2) = make_ulonglong2(accB[t][0], accB[t][1]);
        }
    }
    __syncthreads();
    if (cgrp == 0) {
        const u64* src = s_red + rid * 34;
        const int h = h0 + hr;
        const size_t baseA = ((((size_t)b * H_ + h) * W_ + (w0 + colA)) * D_) * (size_t)F_;
        const size_t baseB = ((((size_t)b * H_ + h) * W_ + (w0 + colB)) * D_) * (size_t)F_;
        #pragma unroll
        for (int t = 0; t < 8; ++t) {
            ulonglong2 pa = *(const ulonglong2*)(src + t * 2);
            ulonglong2 pb = *(const ulonglong2*)(src + 16 + t * 2);
            float* oA = out + baseA + (size_t)(dbase + t) * F_ + fq * 4;
            float* oB = out + baseB + (size_t)(dbase + t) * F_ + fq * 4;
            *(ulonglong2*)oA = make_ulonglong2(add2(accA[t][0], pa.x),
                                               add2(accA[t][1], pa.y));
            *(ulonglong2*)oB = make_ulonglong2(add2(accB[t][0], pb.x),
                                               add2(accB[t][1], pb.y));
        }
    }
}

extern "C" void kernel_launch(void* const* d_in, const int* in_sizes, int n_in,
                              void* d_out, int out_size)
{
    // Identify inputs by element count (robust to metadata order):
    // images 12,582,912 | base_plane 24,576 | kernel 6,912 | default 1
    const float* images = nullptr;
    const int*   bp     = nullptr;
    const float* kern   = nullptr;
    const float* defv   = nullptr;
    for (int i = 0; i < n_in; ++i) {
        switch (in_sizes[i]) {
            case 12582912: images = (const float*)d_in[i]; break;
            case 24576:    bp     = (const int*)  d_in[i]; break;
            case 6912:     kern   = (const float*)d_in[i]; break;
            case 1:        defv   = (const float*)d_in[i]; break;
            default: break;
        }
    }
    if (!images) images = (const float*)d_in[0];
    if (!bp)     bp     = (const int*)  d_in[1];
    if (!kern)   kern   = (const float*)d_in[2];
    if (!defv)   defv   = (const float*)d_in[3];

    const int smem_bytes = SMEM_FLOATS * 4;
    (void)cudaFuncSetAttribute(sparse_conv3d_kernel,
                               cudaFuncAttributeMaxDynamicSharedMemorySize, smem_bytes);

    dim3 grid(W_ / TW, H_ / TH, B_);   // (16, 24, 2)
    sparse_conv3d_kernel<<<grid, 512, smem_bytes>>>(
        images, bp, kern, defv, (float*)d_out);
}

// round 14
// speedup vs baseline: 1.1955x; 1.0677x over previous
#include <cuda_runtime.h>

typedef unsigned long long u64;

// ---- packed fp32x2 helpers (sm_100+; ptxas never emits these from C++) ----
static __device__ __forceinline__ u64 pack2(float x) {
    u64 r; asm("mov.b64 %0, {%1, %1};" : "=l"(r) : "f"(x)); return r;
}
static __device__ __forceinline__ u64 fma2(u64 a, u64 b, u64 c) {
    u64 d; asm("fma.rn.f32x2 %0, %1, %2, %3;" : "=l"(d) : "l"(a), "l"(b), "l"(c)); return d;
}
static __device__ __forceinline__ u64 add2(u64 a, u64 b) {
    u64 d; asm("add.rn.f32x2 %0, %1, %2;" : "=l"(d) : "l"(a), "l"(b)); return d;
}

#define B_  2
#define H_  96
#define W_  128
#define D_  32
#define C_  16
#define F_  16
#define TW  8
#define TH  4                       // output h-rows per CTA
#define NSROW 6                     // slab rows (TH + 2 halo)
#define NSLAB 60                    // 6 x 10
#define DSTR  17                    // [d][c]: c stride 1, d stride 16+1 pad
#define SSTR  561                   // 33 rows * 17 (row 32 = dv row)
#define DVROW 544                   // 32*17
#define IMG_FLOATS (NSLAB * SSTR)   // 33660
#define WOFF   33664                // 16B-aligned weight base
#define WFLOATS (27 * 16 * 16)      // 6912
#define BPOFF  (WOFF + WFLOATS)     // 40576
#define SMEM_FLOATS (BPOFF + 64)    // 40640 floats = 162,560 B -> 1 CTA/SM

extern __shared__ float smem[];

__global__ __launch_bounds__(512, 1)
void sparse_conv3d_kernel(const float* __restrict__ images,
                          const int*   __restrict__ bp,
                          const float* __restrict__ kern,
                          const float* __restrict__ defv,
                          float*       __restrict__ out)
{
    float* s_img = smem;            // [slab][33 rows][17] ; row 32 = dv row
    float* s_w   = smem + WOFF;     // natural [tap][c][f]
    int*   s_bp  = (int*)(smem + BPOFF);

    const int tid = threadIdx.x;    // 512 threads
    const int b   = blockIdx.z;
    const int h0  = blockIdx.y * TH;
    const int w0  = blockIdx.x * TW;
    const float dv = defv[0];

    // ---- stage weights: straight copy, natural layout ----
    for (int idx = tid; idx < WFLOATS / 4; idx += 512) {
        ((float4*)s_w)[idx] = ((const float4*)kern)[idx];
    }
    // ---- dv rows: 60 slabs x 16 c ----
    for (int idx = tid; idx < NSLAB * 16; idx += 512) {
        int s = idx >> 4, c = idx & 15;
        s_img[s * SSTR + DVROW + c] = dv;
    }
    // ---- base planes for 6x10 neighborhood ----
    if (tid < NSLAB) {
        int r  = tid / 10, q = tid - r * 10;
        int hc = min(max(h0 + r - 1, 0), H_ - 1);
        int wc = min(max(w0 + q - 1, 0), W_ - 1);
        s_bp[tid] = bp[(b * H_ + hc) * W_ + wc];
    }
    // ---- stage 60 slabs as [d][c]; spatially invalid slabs = dv ----
    for (int u = tid; u < NSLAB * 128; u += 512) {
        const int s  = u >> 7;
        const int d  = (u >> 2) & 31;
        const int c4 = (u & 3) * 4;
        const int r  = s / 10, q = s - r * 10;
        const int hn = h0 + r - 1;
        const int wn = w0 + q - 1;
        float4 v;
        if ((unsigned)hn < (unsigned)H_ && (unsigned)wn < (unsigned)W_) {
            v = *(const float4*)&images[
                ((((size_t)b * H_ + hn) * W_ + wn) * D_ + d) * C_ + c4];
        } else {
            v = make_float4(dv, dv, dv, dv);
        }
        float* p = s_img + s * SSTR + d * DSTR + c4;
        p[0] = v.x; p[1] = v.y; p[2] = v.z; p[3] = v.w;
    }
    __syncthreads();

    // ---- compute: hr(4) x cgrp(2) x [wlp(4) x fq(4) x dg(4)] ----
    const int hr    = tid >> 7;       // output row within tile
    const int t7    = tid & 127;
    const int cgrp  = t7 >> 6;        // 0: c 0-7, 1: c 8-15
    const int tp    = t7 & 63;
    const int wlp   = tp & 3;         // column pair: cols {2wlp, 2wlp+1}
    const int fq    = (tp >> 2) & 3;  // f in [4fq, 4fq+4)
    const int dg    = tp >> 4;        // 0..3 -> d in [8dg, 8dg+8)
    const int dbase = dg * 8;
    const int cbase = cgrp * 8;
    const int colA  = 2 * wlp;
    const int colB  = colA + 1;
    const int bpA   = s_bp[(hr + 1) * 10 + 1 + colA];
    const int bpB   = s_bp[(hr + 1) * 10 + 1 + colB];

    u64 accA[8][2], accB[8][2];
    #pragma unroll
    for (int t = 0; t < 8; ++t) {
        accA[t][0] = 0ull; accA[t][1] = 0ull;
        accB[t][0] = 0ull; accB[t][1] = 0ull;
    }

    #pragma unroll 1
    for (int i = 0; i < 3; ++i) {
        #pragma unroll 1
        for (int j = 0; j < 3; ++j) {
            const int sA   = (hr + i) * 10 + colA + j;
            const int sB   = sA + 1;
            const int relA = bpA - s_bp[sA];
            const int relB = bpB - s_bp[sB];
            int xoffA[10], xoffB[10];
            #pragma unroll
            for (int u = 0; u < 10; ++u) {
                int ddA  = dbase + relA - 1 + u;
                int ddB  = dbase + relB - 1 + u;
                int rowA = ((unsigned)ddA < (unsigned)D_) ? ddA : 32;
                int rowB = ((unsigned)ddB < (unsigned)D_) ? ddB : 32;
                xoffA[u] = sA * SSTR + rowA * DSTR + cbase;
                xoffB[u] = sB * SSTR + rowB * DSTR + cbase;
            }
            const float* wp = s_w + (i * 3 + j) * 768 + cbase * 16 + fq * 4;
            // FULL unroll: lets ptxas batch LDS across cc iterations (MLP),
            // hiding the 29-cyc smem latency behind prior FFMA2 work.
            #pragma unroll
            for (int cc = 0; cc < 8; ++cc) {
                const float* wc = wp + cc * 16;
                ulonglong2 wk0 = *(const ulonglong2*)(wc);
                ulonglong2 wk1 = *(const ulonglong2*)(wc + 256);
                ulonglong2 wk2 = *(const ulonglong2*)(wc + 512);
                // column A
                {
                    u64 X[10];
                    #pragma unroll
                    for (int u = 0; u < 10; ++u)
                        X[u] = pack2(s_img[xoffA[u] + cc]);
                    #pragma unroll
                    for (int t = 0; t < 8; ++t) {
                        accA[t][0] = fma2(X[t],     wk0.x, accA[t][0]);
                        accA[t][1] = fma2(X[t],     wk0.y, accA[t][1]);
                        accA[t][0] = fma2(X[t + 1], wk1.x, accA[t][0]);
                        accA[t][1] = fma2(X[t + 1], wk1.y, accA[t][1]);
                        accA[t][0] = fma2(X[t + 2], wk2.x, accA[t][0]);
                        accA[t][1] = fma2(X[t + 2], wk2.y, accA[t][1]);
                    }
                }
                // column B
                {
                    u64 X[10];
                    #pragma unroll
                    for (int u = 0; u < 10; ++u)
                        X[u] = pack2(s_img[xoffB[u] + cc]);
                    #pragma unroll
                    for (int t = 0; t < 8; ++t) {
                        accB[t][0] = fma2(X[t],     wk0.x, accB[t][0]);
                        accB[t][1] = fma2(X[t],     wk0.y, accB[t][1]);
                        accB[t][0] = fma2(X[t + 1], wk1.x, accB[t][0]);
                        accB[t][1] = fma2(X[t + 1], wk1.y, accB[t][1]);
                        accB[t][0] = fma2(X[t + 2], wk2.x, accB[t][0]);
                        accB[t][1] = fma2(X[t + 2], wk2.y, accB[t][1]);
                    }
                }
            }
        }
    }

    // ---- reduce c-split: cgrp1 stages 32 u64, cgrp0 adds + stores ----
    __syncthreads();                       // slabs dead; reuse as staging
    u64* s_red = (u64*)smem;               // 256 threads x 34 u64 stride (16B aligned)
    const int rid = hr * 64 + tp;
    if (cgrp == 1) {
        u64* dst = s_red + rid * 34;
        #pragma unroll
        for (int t = 0; t < 8; ++t) {
            *(ulonglong2*)(dst + t * 2)      = make_ulonglong2(accA[t][0], accA[t][1]);
            *(ulonglong2*)(dst + 16 + t * 2) = make_ulonglong2(accB[t][0], accB[t][1]);
        }
    }
    __syncthreads();
    if (cgrp == 0) {
        const u64* src = s_red + rid * 34;
        const int h = h0 + hr;
        const size_t baseA = ((((size_t)b * H_ + h) * W_ + (w0 + colA)) * D_) * (size_t)F_;
        const size_t baseB = ((((size_t)b * H_ + h) * W_ + (w0 + colB)) * D_) * (size_t)F_;
        #pragma unroll
        for (int t = 0; t < 8; ++t) {
            ulonglong2 pa = *(const ulonglong2*)(src + t * 2);
            ulonglong2 pb = *(const ulonglong2*)(src + 16 + t * 2);
            float* oA = out + baseA + (size_t)(dbase + t) * F_ + fq * 4;
            float* oB = out + baseB + (size_t)(dbase + t) * F_ + fq * 4;
            *(ulonglong2*)oA = make_ulonglong2(add2(accA[t][0], pa.x),
                                               add2(accA[t][1], pa.y));
            *(ulonglong2*)oB = make_ulonglong2(add2(accB[t][0], pb.x),
                                               add2(accB[t][1], pb.y));
        }
    }
}

extern "C" void kernel_launch(void* const* d_in, const int* in_sizes, int n_in,
                              void* d_out, int out_size)
{
    // Identify inputs by element count (robust to metadata order):
    // images 12,582,912 | base_plane 24,576 | kernel 6,912 | default 1
    const float* images = nullptr;
    const int*   bp     = nullptr;
    const float* kern   = nullptr;
    const float* defv   = nullptr;
    for (int i = 0; i < n_in; ++i) {
        switch (in_sizes[i]) {
            case 12582912: images = (const float*)d_in[i]; break;
            case 24576:    bp     = (const int*)  d_in[i]; break;
            case 6912:     kern   = (const float*)d_in[i]; break;
            case 1:        defv   = (const float*)d_in[i]; break;
            default: break;
        }
    }
    if (!images) images = (const float*)d_in[0];
    if (!bp)     bp     = (const int*)  d_in[1];
    if (!kern)   kern   = (const float*)d_in[2];
    if (!defv)   defv   = (const float*)d_in[3];

    const int smem_bytes = SMEM_FLOATS * 4;
    (void)cudaFuncSetAttribute(sparse_conv3d_kernel,
                               cudaFuncAttributeMaxDynamicSharedMemorySize, smem_bytes);

    dim3 grid(W_ / TW, H_ / TH, B_);   // (16, 24, 2)
    sparse_conv3d_kernel<<<grid, 512, smem_bytes>>>(
        images, bp, kern, defv, (float*)d_out);
}

// round 15
// speedup vs baseline: 1.2068x; 1.0094x over previous
#include <cuda_runtime.h>

typedef unsigned long long u64;

static __device__ __forceinline__ u64 fma2(u64 a, u64 b, u64 c) {
    u64 d; asm("fma.rn.f32x2 %0, %1, %2, %3;" : "=l"(d) : "l"(a), "l"(b), "l"(c)); return d;
}
static __device__ __forceinline__ float sum2(u64 a) {
    float lo, hi; asm("mov.b64 {%0, %1}, %2;" : "=f"(lo), "=f"(hi) : "l"(a));
    return lo + hi;
}

#define B_  2
#define H_  96
#define W_  128
#define D_  32
#define C_  16
#define F_  16
#define TW  8
#define TH  4                       // output h-rows per CTA
#define NSLAB 60                    // 6 x 10
#define DSTR  18                    // [d][c]: c stride 1, d stride 16+2 (EVEN: 8B-aligned c-pairs)
#define SSTR  596                   // 33*18 + 2 (even; 596 mod 32 = 20 decorrelates cols)
#define DVROW 576                   // 32*18
#define IMG_FLOATS (NSLAB * SSTR)   // 35760
#define WOFF   35760                // 16B-aligned weight base (35760*4 % 16 == 0)
#define WFLOATS (27 * 16 * 16)      // 6912, as w2[tap][cp][f][par]
#define BPOFF  (WOFF + WFLOATS)     // 42672
#define SMEM_FLOATS (BPOFF + 64)    // 42736 floats = 170,944 B -> 1 CTA/SM

extern __shared__ float smem[];

__global__ __launch_bounds__(512, 1)
void sparse_conv3d_kernel(const float* __restrict__ images,
                          const int*   __restrict__ bp,
                          const float* __restrict__ kern,
                          const float* __restrict__ defv,
                          float*       __restrict__ out)
{
    float* s_img = smem;            // [slab][33 rows][18] ; row 32 = dv row
    float* s_w   = smem + WOFF;     // w2[tap][cp(8)][f(16)][2]
    int*   s_bp  = (int*)(smem + BPOFF);

    const int tid = threadIdx.x;    // 512 threads
    const int b   = blockIdx.z;
    const int h0  = blockIdx.y * TH;
    const int w0  = blockIdx.x * TW;
    const float dv = defv[0];

    // ---- stage weights: natural [tap][c][f] -> w2[tap][c>>1][f][c&1] ----
    for (int g = tid; g < WFLOATS; g += 512) {
        int tap = g >> 8;
        int c   = (g >> 4) & 15;
        int f   = g & 15;
        s_w[tap * 256 + (c >> 1) * 32 + f * 2 + (c & 1)] = kern[g];
    }
    // ---- dv rows: 60 slabs x 16 c ----
    for (int idx = tid; idx < NSLAB * 16; idx += 512) {
        int s = idx >> 4, c = idx & 15;
        s_img[s * SSTR + DVROW + c] = dv;
    }
    // ---- base planes for 6x10 neighborhood ----
    if (tid < NSLAB) {
        int r  = tid / 10, q = tid - r * 10;
        int hc = min(max(h0 + r - 1, 0), H_ - 1);
        int wc = min(max(w0 + q - 1, 0), W_ - 1);
        s_bp[tid] = bp[(b * H_ + hc) * W_ + wc];
    }
    // ---- stage 60 slabs as [d][c]; spatially invalid slabs = dv ----
    for (int u = tid; u < NSLAB * 128; u += 512) {
        const int s  = u >> 7;
        const int d  = (u >> 2) & 31;
        const int c4 = (u & 3) * 4;
        const int r  = s / 10, q = s - r * 10;
        const int hn = h0 + r - 1;
        const int wn = w0 + q - 1;
        float4 v;
        if ((unsigned)hn < (unsigned)H_ && (unsigned)wn < (unsigned)W_) {
            v = *(const float4*)&images[
                ((((size_t)b * H_ + hn) * W_ + wn) * D_ + d) * C_ + c4];
        } else {
            v = make_float4(dv, dv, dv, dv);
        }
        // smem word offset = s*596 + d*18 + c4 : even, 8B-aligned (not 16B) -> 2x float2
        float* p = s_img + s * SSTR + d * DSTR + c4;
        *(float2*)(p)     = make_float2(v.x, v.y);
        *(float2*)(p + 2) = make_float2(v.z, v.w);
    }
    __syncthreads();

    // ---- compute: tid = hr(4) | col(8) | fq(4) | dg(4) ----
    const int hr    = tid >> 7;
    const int col   = (tid >> 4) & 7;
    const int fq    = (tid >> 2) & 3;   // f in [4fq, 4fq+4)
    const int dg    = tid & 3;          // d in [8dg, 8dg+8)
    const int dbase = dg * 8;
    const int bpc   = s_bp[(hr + 1) * 10 + 1 + col];

    // acc[t][f]: u64 lanes = (even-c partial, odd-c partial) for output f
    u64 acc[8][4];
    #pragma unroll
    for (int t = 0; t < 8; ++t)
        #pragma unroll
        for (int p = 0; p < 4; ++p) acc[t][p] = 0ull;

    #pragma unroll 1
    for (int i = 0; i < 3; ++i) {
        #pragma unroll 1
        for (int j = 0; j < 3; ++j) {
            const int s   = (hr + i) * 10 + col + j;
            const int rel = bpc - s_bp[s];
            int xoff[10];
            #pragma unroll
            for (int u = 0; u < 10; ++u) {
                int dd  = dbase + rel - 1 + u;
                int row = ((unsigned)dd < (unsigned)D_) ? dd : 32;
                xoff[u] = s * SSTR + row * DSTR;
            }
            const float* wp = s_w + (i * 3 + j) * 768 + fq * 8;
            #pragma unroll
            for (int cp = 0; cp < 8; ++cp) {
                // x c-pairs: one LDS.64 = ready f32x2 operand (no pack MOVs)
                u64 X[10];
                #pragma unroll
                for (int u = 0; u < 10; ++u)
                    X[u] = *(const u64*)(s_img + xoff[u] + cp * 2);
                // weights: per k, 4 f-pairs = 2 LDS.128
                #pragma unroll
                for (int k = 0; k < 3; ++k) {
                    const float* wk = wp + k * 256 + cp * 32;
                    ulonglong2 wa = *(const ulonglong2*)(wk);      // f0, f1
                    ulonglong2 wb = *(const ulonglong2*)(wk + 4);  // f2, f3
                    #pragma unroll
                    for (int t = 0; t < 8; ++t) {
                        const u64 Xv = X[t + k];
                        acc[t][0] = fma2(Xv, wa.x, acc[t][0]);
                        acc[t][1] = fma2(Xv, wa.y, acc[t][1]);
                        acc[t][2] = fma2(Xv, wb.x, acc[t][2]);
                        acc[t][3] = fma2(Xv, wb.y, acc[t][3]);
                    }
                }
            }
        }
    }

    // ---- merge even/odd-c lanes and store (no cross-thread reduction) ----
    const int h = h0 + hr;
    const size_t pixbase = ((((size_t)b * H_ + h) * W_ + (w0 + col)) * D_) * (size_t)F_;
    #pragma unroll
    for (int t = 0; t < 8; ++t) {
        float4 r;
        r.x = sum2(acc[t][0]);
        r.y = sum2(acc[t][1]);
        r.z = sum2(acc[t][2]);
        r.w = sum2(acc[t][3]);
        *(float4*)(out + pixbase + (size_t)(dbase + t) * F_ + fq * 4) = r;
    }
}

extern "C" void kernel_launch(void* const* d_in, const int* in_sizes, int n_in,
                              void* d_out, int out_size)
{
    // Identify inputs by element count (robust to metadata order):
    // images 12,582,912 | base_plane 24,576 | kernel 6,912 | default 1
    const float* images = nullptr;
    const int*   bp     = nullptr;
    const float* kern   = nullptr;
    const float* defv   = nullptr;
    for (int i = 0; i < n_in; ++i) {
        switch (in_sizes[i]) {
            case 12582912: images = (const float*)d_in[i]; break;
            case 24576:    bp     = (const int*)  d_in[i]; break;
            case 6912:     kern   = (const float*)d_in[i]; break;
            case 1:        defv   = (const float*)d_in[i]; break;
            default: break;
        }
    }
    if (!images) images = (const float*)d_in[0];
    if (!bp)     bp     = (const int*)  d_in[1];
    if (!kern)   kern   = (const float*)d_in[2];
    if (!defv)   defv   = (const float*)d_in[3];

    const int smem_bytes = SMEM_FLOATS * 4;
    (void)cudaFuncSetAttribute(sparse_conv3d_kernel,
                               cudaFuncAttributeMaxDynamicSharedMemorySize, smem_bytes);

    dim3 grid(W_ / TW, H_ / TH, B_);   // (16, 24, 2)
    sparse_conv3d_kernel<<<grid, 512, smem_bytes>>>(
        images, bp, kern, defv, (float*)d_out);
}